// round 9
// baseline (speedup 1.0000x reference)
#include <cuda_runtime.h>
#include <cuda_fp16.h>
#include <cstdint>
#include <cstddef>

#define B_ 32
#define S_ 128
#define T_ 128
#define V_ 32000
#define E_ 256
#define H_ 256
#define NEGV -1.0e9f

// ================= scratch (static device memory; no allocation) =================
__device__ float g_P_enc[B_ * S_ * H_];
__device__ float g_P_dec[B_ * T_ * H_];
__device__ float g_enc_out[B_ * S_ * H_];
__device__ float g_h_final[B_ * H_];
__device__ float g_Hdec[B_ * T_ * H_];
__device__ float g_comb[B_ * T_ * 2 * H_];
__device__ __half g_Wh[V_ * H_];           // W_out in fp16
__device__ __half g_Ah[B_ * T_ * H_];      // attn_out in fp16

// ================= PTX helpers (sm_80-compatible only; no 'a' features) =================
__device__ __forceinline__ uint32_t smem_u32(const void* p) {
    uint32_t a;
    asm("{ .reg .u64 t; cvta.to.shared.u64 t, %1; cvt.u32.u64 %0, t; }" : "=r"(a) : "l"(p));
    return a;
}
#define CP_ASYNC16(saddr, gaddr) \
    asm volatile("cp.async.cg.shared.global [%0], [%1], 16;" :: "r"(saddr), "l"(gaddr))
#define CP_COMMIT() asm volatile("cp.async.commit_group;")
#define CP_WAIT0()  asm volatile("cp.async.wait_group 0;")
#define LDSM_X4(r, addr) \
    asm volatile("ldmatrix.sync.aligned.m8n8.x4.shared.b16 {%0,%1,%2,%3}, [%4];" \
        : "=r"((r)[0]), "=r"((r)[1]), "=r"((r)[2]), "=r"((r)[3]) : "r"(addr))
#define MMA16816F16(d, a, b) \
    asm volatile("mma.sync.aligned.m16n8k16.row.col.f32.f16.f16.f32 " \
        "{%0,%1,%2,%3}, {%4,%5,%6,%7}, {%8,%9}, {%0,%1,%2,%3};" \
        : "+f"((d)[0]), "+f"((d)[1]), "+f"((d)[2]), "+f"((d)[3]) \
        : "r"((a)[0]), "r"((a)[1]), "r"((a)[2]), "r"((a)[3]), "r"((b)[0]), "r"((b)[1]))

// ================= fp32 -> fp16 convert (vector of 4) =================
__global__ void k_cvt4h(const float4* __restrict__ x, __half* __restrict__ o) {
    int i = blockIdx.x * blockDim.x + threadIdx.x;
    float4 v = x[i];
    __half2* O = (__half2*)(o + (size_t)i * 4);
    O[0] = __halves2half2(__float2half_rn(v.x), __float2half_rn(v.y));
    O[1] = __halves2half2(__float2half_rn(v.z), __float2half_rn(v.w));
}

// ================= mma.sync fp16 logits GEMM =================
// C[4096,32000] = A@W^T + bias ; fp16 inputs, fp32 accumulate.
#define LG_STRIDE 144
#define LG_MAT (128 * LG_STRIDE)
#define LG_A 0
#define LG_W (LG_MAT)
#define LG_BUF (2 * LG_MAT)               // 36864 B per buffer
#define SMEM_LOGITS (2 * LG_BUF)          // 73728 B

__device__ __forceinline__ void lg_load(
    uint32_t sb, const __half* __restrict__ Ah, const __half* __restrict__ Wh,
    int m0, int n0, int kc, int tid) {
#pragma unroll
    for (int i = 0; i < 4; i++) {
        int idx = tid + i * 256;
        int r = idx >> 3, c = idx & 7;
        uint32_t soff = r * LG_STRIDE + c * 16;
        size_t ga = (size_t)(m0 + r) * H_ + kc * 64 + c * 8;
        size_t gw = (size_t)(n0 + r) * H_ + kc * 64 + c * 8;
        CP_ASYNC16(sb + LG_A + soff, Ah + ga);
        CP_ASYNC16(sb + LG_W + soff, Wh + gw);
    }
}

__global__ __launch_bounds__(256, 2) void k_logits_mma(
    const __half* __restrict__ Ah, const __half* __restrict__ Wh,
    const float* __restrict__ bias, float* __restrict__ out) {
    extern __shared__ char smem[];
    const uint32_t sbase = smem_u32(smem);
    const int tid = threadIdx.x, wid = tid >> 5, lane = tid & 31;
    const int warp_m = wid & 3, warp_n = wid >> 2;
    const int m0 = blockIdx.x * 128;
    const int n0 = blockIdx.y * 128;

    float acc[2][8][4];
#pragma unroll
    for (int mt = 0; mt < 2; mt++)
#pragma unroll
        for (int nt = 0; nt < 8; nt++)
#pragma unroll
            for (int q = 0; q < 4; q++) acc[mt][nt][q] = 0.0f;

    lg_load(sbase, Ah, Wh, m0, n0, 0, tid);
    CP_COMMIT();
    CP_WAIT0();
    __syncthreads();

    const int g = lane >> 3, r8 = lane & 7;
    const uint32_t a_off = (uint32_t)(warp_m * 32 + (g & 1) * 8 + r8) * LG_STRIDE +
                           (uint32_t)((g >> 1) * 8) * 2;
    const uint32_t b_off = (uint32_t)(warp_n * 64 + (g >> 1) * 8 + r8) * LG_STRIDE +
                           (uint32_t)((g & 1) * 8) * 2;

    for (int kc = 0; kc < 4; kc++) {
        const uint32_t buf = sbase + (kc & 1) * LG_BUF;
        if (kc < 3) {
            lg_load(sbase + ((kc + 1) & 1) * LG_BUF, Ah, Wh, m0, n0, kc + 1, tid);
            CP_COMMIT();
        }
#pragma unroll
        for (int ks = 0; ks < 4; ks++) {
            const uint32_t koff = (uint32_t)(ks * 16) * 2;
            uint32_t af[2][4], bf[8][2];
#pragma unroll
            for (int p = 0; p < 4; p++) {
                uint32_t t[4];
                LDSM_X4(t, buf + LG_W + b_off + p * (16 * LG_STRIDE) + koff);
                bf[2 * p][0] = t[0]; bf[2 * p][1] = t[1];
                bf[2 * p + 1][0] = t[2]; bf[2 * p + 1][1] = t[3];
            }
#pragma unroll
            for (int mt = 0; mt < 2; mt++)
                LDSM_X4(af[mt], buf + LG_A + a_off + mt * (16 * LG_STRIDE) + koff);
#pragma unroll
            for (int mt = 0; mt < 2; mt++)
#pragma unroll
                for (int nt = 0; nt < 8; nt++) MMA16816F16(acc[mt][nt], af[mt], bf[nt]);
        }
        if (kc < 3) {
            CP_WAIT0();
            __syncthreads();
        }
    }

    const int er = lane >> 2, ec = (lane & 3) * 2;
#pragma unroll
    for (int mt = 0; mt < 2; mt++) {
        const int row0 = m0 + warp_m * 32 + mt * 16 + er;
#pragma unroll
        for (int nt = 0; nt < 8; nt++) {
            const int col0 = n0 + warp_n * 64 + nt * 8 + ec;
            float2 bb = *(const float2*)(bias + col0);
            float2 o0, o1;
            o0.x = acc[mt][nt][0] + bb.x; o0.y = acc[mt][nt][1] + bb.y;
            o1.x = acc[mt][nt][2] + bb.x; o1.y = acc[mt][nt][3] + bb.y;
            *(float2*)(out + (size_t)row0 * V_ + col0) = o0;
            *(float2*)(out + (size_t)(row0 + 8) * V_ + col0) = o1;
        }
    }
}

// ================= generic fp32 SIMT GEMM (small ops only) =================
template <int BM, int BN, int BK, int TM, int TN>
__global__ __launch_bounds__(256) void k_gemm(
    int M, int N, int K,
    const float* __restrict__ A, const int* __restrict__ gidx,
    const float* __restrict__ Bm, float* __restrict__ C,
    const float* __restrict__ bias1, const float* __restrict__ bias2, int act,
    __half* __restrict__ Ch) {
    constexpr int KV = BK / 4;
    constexpr int RPP = 256 / KV;
    constexpr int AP = BM / RPP;
    constexpr int BP = BN / RPP;

    __shared__ __align__(16) float As[2][BK][BM];
    __shared__ __align__(16) float Bs[2][BK][BN];

    const int tid = threadIdx.x;
    const int m0 = blockIdx.y * BM;
    const int n0 = blockIdx.x * BN;
    const int lr = tid / KV;
    const int lk = tid % KV;

    const float* ap[AP];
    const float* bp[BP];
#pragma unroll
    for (int p = 0; p < AP; p++) {
        int gm = m0 + lr + p * RPP;
        int grow = gidx ? gidx[gm] : gm;
        ap[p] = A + (size_t)grow * K + lk * 4;
    }
#pragma unroll
    for (int p = 0; p < BP; p++)
        bp[p] = Bm + (size_t)(n0 + lr + p * RPP) * K + lk * 4;

    float acc[TM][TN];
#pragma unroll
    for (int i = 0; i < TM; i++)
#pragma unroll
        for (int j = 0; j < TN; j++) acc[i][j] = 0.0f;

    float4 ar[AP], br[BP];
#pragma unroll
    for (int p = 0; p < AP; p++) ar[p] = *(const float4*)(ap[p]);
#pragma unroll
    for (int p = 0; p < BP; p++) br[p] = *(const float4*)(bp[p]);
#pragma unroll
    for (int p = 0; p < AP; p++) {
        int m = lr + p * RPP;
        As[0][lk * 4 + 0][m] = ar[p].x; As[0][lk * 4 + 1][m] = ar[p].y;
        As[0][lk * 4 + 2][m] = ar[p].z; As[0][lk * 4 + 3][m] = ar[p].w;
    }
#pragma unroll
    for (int p = 0; p < BP; p++) {
        int n = lr + p * RPP;
        Bs[0][lk * 4 + 0][n] = br[p].x; Bs[0][lk * 4 + 1][n] = br[p].y;
        Bs[0][lk * 4 + 2][n] = br[p].z; Bs[0][lk * 4 + 3][n] = br[p].w;
    }
    __syncthreads();

    const int NT = K / BK;
    const int trow = tid / (BN / TN);
    const int tcol = tid % (BN / TN);

    for (int kt = 0; kt < NT; kt++) {
        const int cur = kt & 1;
        if (kt + 1 < NT) {
#pragma unroll
            for (int p = 0; p < AP; p++) ar[p] = *(const float4*)(ap[p] + (kt + 1) * BK);
#pragma unroll
            for (int p = 0; p < BP; p++) br[p] = *(const float4*)(bp[p] + (kt + 1) * BK);
        }
#pragma unroll
        for (int k = 0; k < BK; k++) {
            float a[TM], bf[TN];
#pragma unroll
            for (int i = 0; i < TM; i += 4) {
                float4 v = *(const float4*)&As[cur][k][trow * TM + i];
                a[i] = v.x; a[i + 1] = v.y; a[i + 2] = v.z; a[i + 3] = v.w;
            }
#pragma unroll
            for (int j = 0; j < TN; j += 4) {
                float4 v = *(const float4*)&Bs[cur][k][tcol * TN + j];
                bf[j] = v.x; bf[j + 1] = v.y; bf[j + 2] = v.z; bf[j + 3] = v.w;
            }
#pragma unroll
            for (int i = 0; i < TM; i++)
#pragma unroll
                for (int j = 0; j < TN; j++) acc[i][j] += a[i] * bf[j];
        }
        if (kt + 1 < NT) {
            const int nxt = cur ^ 1;
#pragma unroll
            for (int p = 0; p < AP; p++) {
                int m = lr + p * RPP;
                As[nxt][lk * 4 + 0][m] = ar[p].x; As[nxt][lk * 4 + 1][m] = ar[p].y;
                As[nxt][lk * 4 + 2][m] = ar[p].z; As[nxt][lk * 4 + 3][m] = ar[p].w;
            }
#pragma unroll
            for (int p = 0; p < BP; p++) {
                int n = lr + p * RPP;
                Bs[nxt][lk * 4 + 0][n] = br[p].x; Bs[nxt][lk * 4 + 1][n] = br[p].y;
                Bs[nxt][lk * 4 + 2][n] = br[p].z; Bs[nxt][lk * 4 + 3][n] = br[p].w;
            }
            __syncthreads();
        }
    }

    float bv[TN];
#pragma unroll
    for (int j = 0; j < TN; j++) {
        int n = n0 + tcol * TN + j;
        float v = bias1 ? bias1[n] : 0.0f;
        if (bias2) v += bias2[n];
        bv[j] = v;
    }
#pragma unroll
    for (int i = 0; i < TM; i++) {
        int m = m0 + trow * TM + i;
#pragma unroll
        for (int j = 0; j < TN; j += 4) {
            float4 o;
            o.x = acc[i][j + 0] + bv[j + 0];
            o.y = acc[i][j + 1] + bv[j + 1];
            o.z = acc[i][j + 2] + bv[j + 2];
            o.w = acc[i][j + 3] + bv[j + 3];
            if (act) { o.x = tanhf(o.x); o.y = tanhf(o.y); o.z = tanhf(o.z); o.w = tanhf(o.w); }
            if (Ch) {
                __half* crow = Ch + (size_t)m * N + n0 + tcol * TN;
                *(__half2*)(crow + j) = __halves2half2(__float2half_rn(o.x), __float2half_rn(o.y));
                *(__half2*)(crow + j + 2) = __halves2half2(__float2half_rn(o.z), __float2half_rn(o.w));
            } else {
                float* crow = C + (size_t)m * N + n0 + tcol * TN;
                *(float4*)(crow + j) = o;
            }
        }
    }
}

// ================= RNN recurrence: weights SM-resident, FULL fp32 =================
// One CTA per batch element. out_j = tanh(P + sum_k h[k]*W[j][k]).
// Rows k in [0,64): fp32 in registers. Rows k in [64,256): fp32 float2-PAIRS in smem,
// k-major layout wsm[i][j] = (W[j][64+2i], W[j][64+2i+1]) -> lane-consecutive LDS.64,
// conflict-free, ZERO conversion instructions. h double-buffered -> 1 sync/step.
#define RNN_WPAIRS (96 * 256)                      // float2 count
#define RNN_SMEM (RNN_WPAIRS * 8 + 2 * H_ * 4)     // 198656 B

__global__ __launch_bounds__(256) void k_rnn(
    const float* __restrict__ P, const float* __restrict__ W,   // W = W_hh [H][H]
    const int* __restrict__ lengths, const float* __restrict__ h0,
    float* __restrict__ outSeq, float* __restrict__ hFin,
    float* __restrict__ combHalf, int steps) {
    extern __shared__ float sm[];
    float2* wsm = (float2*)sm;                   // [96][256]
    float* hs = sm + RNN_WPAIRS * 2;             // 2 buffers of H_
    const int b = blockIdx.x;
    const int j = threadIdx.x;

    // stage: thread j owns row j of W (contiguous in k)
    const float* wrow = W + (size_t)j * H_;
    float wreg[64];
#pragma unroll
    for (int i = 0; i < 64; i += 4) {
        float4 w4 = *(const float4*)(wrow + i);
        wreg[i] = w4.x; wreg[i + 1] = w4.y; wreg[i + 2] = w4.z; wreg[i + 3] = w4.w;
    }
#pragma unroll 8
    for (int i = 0; i < 96; i++)
        wsm[i * 256 + j] = *(const float2*)(wrow + 64 + 2 * i);
    hs[j] = h0 ? h0[b * H_ + j] : 0.0f;
    __syncthreads();

    const int len = lengths ? lengths[b] : steps;
    const float* Pb = P + (size_t)b * steps * H_;
    float* Ob = outSeq + (size_t)b * steps * H_;
    int cur = 0;

    for (int t = 0; t < steps; t++) {
        const float* hc = hs + cur * H_;
        float* hnx = hs + (cur ^ 1) * H_;
        float pv = Pb[t * H_ + j];
        float a0 = 0.f, a1 = 0.f, a2 = 0.f, a3 = 0.f;
#pragma unroll
        for (int k = 0; k < 64; k += 4) {
            float4 h4 = *(const float4*)(hc + k);
            a0 += h4.x * wreg[k];     a1 += h4.y * wreg[k + 1];
            a2 += h4.z * wreg[k + 2]; a3 += h4.w * wreg[k + 3];
        }
#pragma unroll
        for (int i = 0; i < 96; i += 2) {
            float4 h4 = *(const float4*)(hc + 64 + 2 * i);
            float2 fa = wsm[i * 256 + j];
            float2 fb = wsm[(i + 1) * 256 + j];
            a0 += h4.x * fa.x; a1 += h4.y * fa.y;
            a2 += h4.z * fb.x; a3 += h4.w * fb.y;
        }
        float hv = tanhf(pv + ((a0 + a1) + (a2 + a3)));
        bool valid = t < len;
        hnx[j] = valid ? hv : hc[j];
        Ob[t * H_ + j] = valid ? hv : 0.0f;
        if (combHalf)
            combHalf[((size_t)(b * steps + t)) * (2 * H_) + H_ + j] = hv;
        __syncthreads();
        cur ^= 1;
    }
    if (hFin) hFin[b * H_ + j] = hs[cur * H_ + j];
}

// ================= fused attention: scores -> softmax -> context =================
__global__ __launch_bounds__(256) void k_attn(
    const float* __restrict__ Hdec, const float* __restrict__ enc,
    const int* __restrict__ idx_de, float* __restrict__ comb) {
    const int b = blockIdx.x;
    const int t0 = blockIdx.y * 16;
    const int tid = threadIdx.x;
    __shared__ __align__(16) float hs[16][H_];
    __shared__ float sc[16][132];
    __shared__ int msk[S_];

    const float4* Hb4 = (const float4*)(Hdec + ((size_t)b * T_ + t0) * H_);
#pragma unroll
    for (int i = 0; i < 4; i++)
        ((float4*)hs)[tid + i * 256] = Hb4[tid + i * 256];
    if (tid < S_) msk[tid] = idx_de[b * S_ + tid];
    __syncthreads();

    const float* Eb = enc + (size_t)b * S_ * H_;
    {
        const int ti = tid >> 4, sg = tid & 15;
        const float4* h4 = (const float4*)hs[ti];
        for (int r = 0; r < 8; r++) {
            int s = r * 16 + sg;
            const float4* e4 = (const float4*)(Eb + s * H_);
            float a0 = 0.f, a1 = 0.f, a2 = 0.f, a3 = 0.f;
#pragma unroll 8
            for (int k = 0; k < H_ / 4; k++) {
                float4 e = e4[k], h = h4[k];
                a0 += e.x * h.x; a1 += e.y * h.y;
                a2 += e.z * h.z; a3 += e.w * h.w;
            }
            sc[ti][s] = (msk[s] == 0) ? NEGV : ((a0 + a1) + (a2 + a3));
        }
    }
    __syncthreads();
    {
        const int w = tid >> 5, lane = tid & 31;
#pragma unroll
        for (int rr = 0; rr < 2; rr++) {
            int row = w * 2 + rr;
            float v0 = sc[row][lane], v1 = sc[row][lane + 32];
            float v2 = sc[row][lane + 64], v3 = sc[row][lane + 96];
            float m = fmaxf(fmaxf(v0, v1), fmaxf(v2, v3));
#pragma unroll
            for (int o = 16; o > 0; o >>= 1)
                m = fmaxf(m, __shfl_xor_sync(0xffffffffu, m, o));
            float e0 = expf(v0 - m), e1 = expf(v1 - m);
            float e2 = expf(v2 - m), e3 = expf(v3 - m);
            float sum = (e0 + e1) + (e2 + e3);
#pragma unroll
            for (int o = 16; o > 0; o >>= 1)
                sum += __shfl_xor_sync(0xffffffffu, sum, o);
            float inv = 1.0f / sum;
            sc[row][lane] = e0 * inv; sc[row][lane + 32] = e1 * inv;
            sc[row][lane + 64] = e2 * inv; sc[row][lane + 96] = e3 * inv;
        }
    }
    __syncthreads();
    {
        const int ti = tid & 15, jg = tid >> 4;
        float4 c0 = {0, 0, 0, 0}, c1 = c0, c2 = c0, c3 = c0;
        for (int s = 0; s < S_; s++) {
            float p = sc[ti][s];
            const float4* e4 = (const float4*)(Eb + s * H_ + jg * 16);
            float4 e0 = e4[0], e1 = e4[1], e2 = e4[2], e3 = e4[3];
            c0.x += p * e0.x; c0.y += p * e0.y; c0.z += p * e0.z; c0.w += p * e0.w;
            c1.x += p * e1.x; c1.y += p * e1.y; c1.z += p * e1.z; c1.w += p * e1.w;
            c2.x += p * e2.x; c2.y += p * e2.y; c2.z += p * e2.z; c2.w += p * e2.w;
            c3.x += p * e3.x; c3.y += p * e3.y; c3.z += p * e3.z; c3.w += p * e3.w;
        }
        float* dst = comb + ((size_t)(b * T_ + t0 + ti)) * (2 * H_) + jg * 16;
        ((float4*)dst)[0] = c0; ((float4*)dst)[1] = c1;
        ((float4*)dst)[2] = c2; ((float4*)dst)[3] = c3;
    }
}

// ================= launch =================
extern "C" void kernel_launch(void* const* d_in, const int* in_sizes, int n_in,
                              void* d_out, int out_size) {
    const int* indices_de = (const int*)d_in[0];
    const int* lengths_de = (const int*)d_in[1];
    const int* indices_en = (const int*)d_in[2];
    const float* emb_enc = (const float*)d_in[4];
    const float* emb_dec = (const float*)d_in[5];
    const float* W_ih_enc = (const float*)d_in[6];
    const float* W_hh_enc = (const float*)d_in[7];
    const float* b_ih_enc = (const float*)d_in[8];
    const float* b_hh_enc = (const float*)d_in[9];
    const float* W_ih_dec = (const float*)d_in[10];
    const float* W_hh_dec = (const float*)d_in[11];
    const float* b_ih_dec = (const float*)d_in[12];
    const float* b_hh_dec = (const float*)d_in[13];
    const float* W_attn = (const float*)d_in[14];
    const float* b_attn = (const float*)d_in[15];
    const float* W_out = (const float*)d_in[16];
    const float* b_out = (const float*)d_in[17];
    float* out = (float*)d_out;

    float *pPe, *pPd, *pEnc, *pHf, *pHd, *pComb;
    __half *pWh, *pAh;
    cudaGetSymbolAddress((void**)&pPe, g_P_enc);
    cudaGetSymbolAddress((void**)&pPd, g_P_dec);
    cudaGetSymbolAddress((void**)&pEnc, g_enc_out);
    cudaGetSymbolAddress((void**)&pHf, g_h_final);
    cudaGetSymbolAddress((void**)&pHd, g_Hdec);
    cudaGetSymbolAddress((void**)&pComb, g_comb);
    cudaGetSymbolAddress((void**)&pWh, g_Wh);
    cudaGetSymbolAddress((void**)&pAh, g_Ah);

    cudaFuncSetAttribute(k_logits_mma, cudaFuncAttributeMaxDynamicSharedMemorySize,
                         SMEM_LOGITS);
    cudaFuncSetAttribute(k_rnn, cudaFuncAttributeMaxDynamicSharedMemorySize,
                         RNN_SMEM);

    // 1. convert W_out to fp16
    k_cvt4h<<<(V_ * H_ / 4) / 256, 256>>>((const float4*)W_out, pWh);

    // 2. batched input projections (embedding gather fused into GEMM)
    k_gemm<64, 64, 16, 4, 4><<<dim3(H_ / 64, (B_ * S_) / 64), 256>>>(
        B_ * S_, H_, E_, emb_enc, indices_de, W_ih_enc, pPe, b_ih_enc, b_hh_enc, 0, nullptr);
    k_gemm<64, 64, 16, 4, 4><<<dim3(H_ / 64, (B_ * T_) / 64), 256>>>(
        B_ * T_, H_, E_, emb_dec, indices_en, W_ih_dec, pPd, b_ih_dec, b_hh_dec, 0, nullptr);

    // 3. sequential recurrences (weights SM-resident, full fp32)
    k_rnn<<<B_, 256, RNN_SMEM>>>(pPe, W_hh_enc, lengths_de, nullptr, pEnc, pHf, nullptr, S_);
    k_rnn<<<B_, 256, RNN_SMEM>>>(pPd, W_hh_dec, nullptr, pHf, pHd, nullptr, pComb, T_);

    // 4. attention -> context into comb[:, 0:H]
    k_attn<<<dim3(B_, T_ / 16), 256>>>(pHd, pEnc, indices_de, pComb);

    // 5. attn_out = tanh([context|h] @ W_attn^T + b_attn), written directly as fp16
    k_gemm<64, 64, 16, 4, 4><<<dim3(H_ / 64, (B_ * T_) / 64), 256>>>(
        B_ * T_, H_, 2 * H_, pComb, nullptr, W_attn, nullptr, b_attn, nullptr, 1, pAh);

    // 6. mma.sync fp16 logits GEMM
    k_logits_mma<<<dim3((B_ * T_) / 128, V_ / 128), 256, SMEM_LOGITS>>>(
        pAh, pWh, b_out, out);
}

// round 10
// speedup vs baseline: 1.1775x; 1.1775x over previous
#include <cuda_runtime.h>
#include <cuda_fp16.h>
#include <cstdint>
#include <cstddef>

#define B_ 32
#define S_ 128
#define T_ 128
#define V_ 32000
#define E_ 256
#define H_ 256
#define NEGV -1.0e9f

// ================= scratch (static device memory; no allocation) =================
__device__ float g_P_enc[B_ * S_ * H_];
__device__ float g_P_dec[B_ * T_ * H_];
__device__ float g_enc_out[B_ * S_ * H_];
__device__ float g_h_final[B_ * H_];
__device__ float g_Hdec[B_ * T_ * H_];
__device__ float g_comb[B_ * T_ * 2 * H_];
__device__ __half g_Wh[V_ * H_];           // W_out in fp16
__device__ __half g_Ah[B_ * T_ * H_];      // attn_out in fp16

// ================= PTX helpers (sm_80-compatible only; no 'a' features) =================
__device__ __forceinline__ uint32_t smem_u32(const void* p) {
    uint32_t a;
    asm("{ .reg .u64 t; cvta.to.shared.u64 t, %1; cvt.u32.u64 %0, t; }" : "=r"(a) : "l"(p));
    return a;
}
#define CP_ASYNC16(saddr, gaddr) \
    asm volatile("cp.async.cg.shared.global [%0], [%1], 16;" :: "r"(saddr), "l"(gaddr))
#define CP_COMMIT() asm volatile("cp.async.commit_group;")
#define CP_WAIT0()  asm volatile("cp.async.wait_group 0;")
#define LDSM_X4(r, addr) \
    asm volatile("ldmatrix.sync.aligned.m8n8.x4.shared.b16 {%0,%1,%2,%3}, [%4];" \
        : "=r"((r)[0]), "=r"((r)[1]), "=r"((r)[2]), "=r"((r)[3]) : "r"(addr))
#define MMA16816F16(d, a, b) \
    asm volatile("mma.sync.aligned.m16n8k16.row.col.f32.f16.f16.f32 " \
        "{%0,%1,%2,%3}, {%4,%5,%6,%7}, {%8,%9}, {%0,%1,%2,%3};" \
        : "+f"((d)[0]), "+f"((d)[1]), "+f"((d)[2]), "+f"((d)[3]) \
        : "r"((a)[0]), "r"((a)[1]), "r"((a)[2]), "r"((a)[3]), "r"((b)[0]), "r"((b)[1]))

// ================= fp32 -> fp16 convert (vector of 4) =================
__global__ void k_cvt4h(const float4* __restrict__ x, __half* __restrict__ o) {
    int i = blockIdx.x * blockDim.x + threadIdx.x;
    float4 v = x[i];
    __half2* O = (__half2*)(o + (size_t)i * 4);
    O[0] = __halves2half2(__float2half_rn(v.x), __float2half_rn(v.y));
    O[1] = __halves2half2(__float2half_rn(v.z), __float2half_rn(v.w));
}

// ================= mma.sync fp16 logits GEMM =================
#define LG_STRIDE 144
#define LG_MAT (128 * LG_STRIDE)
#define LG_A 0
#define LG_W (LG_MAT)
#define LG_BUF (2 * LG_MAT)               // 36864 B per buffer
#define SMEM_LOGITS (2 * LG_BUF)          // 73728 B

__device__ __forceinline__ void lg_load(
    uint32_t sb, const __half* __restrict__ Ah, const __half* __restrict__ Wh,
    int m0, int n0, int kc, int tid) {
#pragma unroll
    for (int i = 0; i < 4; i++) {
        int idx = tid + i * 256;
        int r = idx >> 3, c = idx & 7;
        uint32_t soff = r * LG_STRIDE + c * 16;
        size_t ga = (size_t)(m0 + r) * H_ + kc * 64 + c * 8;
        size_t gw = (size_t)(n0 + r) * H_ + kc * 64 + c * 8;
        CP_ASYNC16(sb + LG_A + soff, Ah + ga);
        CP_ASYNC16(sb + LG_W + soff, Wh + gw);
    }
}

__global__ __launch_bounds__(256, 2) void k_logits_mma(
    const __half* __restrict__ Ah, const __half* __restrict__ Wh,
    const float* __restrict__ bias, float* __restrict__ out) {
    extern __shared__ char smem[];
    const uint32_t sbase = smem_u32(smem);
    const int tid = threadIdx.x, wid = tid >> 5, lane = tid & 31;
    const int warp_m = wid & 3, warp_n = wid >> 2;
    const int m0 = blockIdx.x * 128;
    const int n0 = blockIdx.y * 128;

    float acc[2][8][4];
#pragma unroll
    for (int mt = 0; mt < 2; mt++)
#pragma unroll
        for (int nt = 0; nt < 8; nt++)
#pragma unroll
            for (int q = 0; q < 4; q++) acc[mt][nt][q] = 0.0f;

    lg_load(sbase, Ah, Wh, m0, n0, 0, tid);
    CP_COMMIT();
    CP_WAIT0();
    __syncthreads();

    const int g = lane >> 3, r8 = lane & 7;
    const uint32_t a_off = (uint32_t)(warp_m * 32 + (g & 1) * 8 + r8) * LG_STRIDE +
                           (uint32_t)((g >> 1) * 8) * 2;
    const uint32_t b_off = (uint32_t)(warp_n * 64 + (g >> 1) * 8 + r8) * LG_STRIDE +
                           (uint32_t)((g & 1) * 8) * 2;

    for (int kc = 0; kc < 4; kc++) {
        const uint32_t buf = sbase + (kc & 1) * LG_BUF;
        if (kc < 3) {
            lg_load(sbase + ((kc + 1) & 1) * LG_BUF, Ah, Wh, m0, n0, kc + 1, tid);
            CP_COMMIT();
        }
#pragma unroll
        for (int ks = 0; ks < 4; ks++) {
            const uint32_t koff = (uint32_t)(ks * 16) * 2;
            uint32_t af[2][4], bf[8][2];
#pragma unroll
            for (int p = 0; p < 4; p++) {
                uint32_t t[4];
                LDSM_X4(t, buf + LG_W + b_off + p * (16 * LG_STRIDE) + koff);
                bf[2 * p][0] = t[0]; bf[2 * p][1] = t[1];
                bf[2 * p + 1][0] = t[2]; bf[2 * p + 1][1] = t[3];
            }
#pragma unroll
            for (int mt = 0; mt < 2; mt++)
                LDSM_X4(af[mt], buf + LG_A + a_off + mt * (16 * LG_STRIDE) + koff);
#pragma unroll
            for (int mt = 0; mt < 2; mt++)
#pragma unroll
                for (int nt = 0; nt < 8; nt++) MMA16816F16(acc[mt][nt], af[mt], bf[nt]);
        }
        if (kc < 3) {
            CP_WAIT0();
            __syncthreads();
        }
    }

    const int er = lane >> 2, ec = (lane & 3) * 2;
#pragma unroll
    for (int mt = 0; mt < 2; mt++) {
        const int row0 = m0 + warp_m * 32 + mt * 16 + er;
#pragma unroll
        for (int nt = 0; nt < 8; nt++) {
            const int col0 = n0 + warp_n * 64 + nt * 8 + ec;
            float2 bb = *(const float2*)(bias + col0);
            float2 o0, o1;
            o0.x = acc[mt][nt][0] + bb.x; o0.y = acc[mt][nt][1] + bb.y;
            o1.x = acc[mt][nt][2] + bb.x; o1.y = acc[mt][nt][3] + bb.y;
            *(float2*)(out + (size_t)row0 * V_ + col0) = o0;
            *(float2*)(out + (size_t)(row0 + 8) * V_ + col0) = o1;
        }
    }
}

// ================= generic fp32 SIMT GEMM (small ops only) =================
template <int BM, int BN, int BK, int TM, int TN>
__global__ __launch_bounds__(256) void k_gemm(
    int M, int N, int K,
    const float* __restrict__ A, const int* __restrict__ gidx,
    const float* __restrict__ Bm, float* __restrict__ C,
    const float* __restrict__ bias1, const float* __restrict__ bias2, int act,
    __half* __restrict__ Ch) {
    constexpr int KV = BK / 4;
    constexpr int RPP = 256 / KV;
    constexpr int AP = BM / RPP;
    constexpr int BP = BN / RPP;

    __shared__ __align__(16) float As[2][BK][BM];
    __shared__ __align__(16) float Bs[2][BK][BN];

    const int tid = threadIdx.x;
    const int m0 = blockIdx.y * BM;
    const int n0 = blockIdx.x * BN;
    const int lr = tid / KV;
    const int lk = tid % KV;

    const float* ap[AP];
    const float* bp[BP];
#pragma unroll
    for (int p = 0; p < AP; p++) {
        int gm = m0 + lr + p * RPP;
        int grow = gidx ? gidx[gm] : gm;
        ap[p] = A + (size_t)grow * K + lk * 4;
    }
#pragma unroll
    for (int p = 0; p < BP; p++)
        bp[p] = Bm + (size_t)(n0 + lr + p * RPP) * K + lk * 4;

    float acc[TM][TN];
#pragma unroll
    for (int i = 0; i < TM; i++)
#pragma unroll
        for (int j = 0; j < TN; j++) acc[i][j] = 0.0f;

    float4 ar[AP], br[BP];
#pragma unroll
    for (int p = 0; p < AP; p++) ar[p] = *(const float4*)(ap[p]);
#pragma unroll
    for (int p = 0; p < BP; p++) br[p] = *(const float4*)(bp[p]);
#pragma unroll
    for (int p = 0; p < AP; p++) {
        int m = lr + p * RPP;
        As[0][lk * 4 + 0][m] = ar[p].x; As[0][lk * 4 + 1][m] = ar[p].y;
        As[0][lk * 4 + 2][m] = ar[p].z; As[0][lk * 4 + 3][m] = ar[p].w;
    }
#pragma unroll
    for (int p = 0; p < BP; p++) {
        int n = lr + p * RPP;
        Bs[0][lk * 4 + 0][n] = br[p].x; Bs[0][lk * 4 + 1][n] = br[p].y;
        Bs[0][lk * 4 + 2][n] = br[p].z; Bs[0][lk * 4 + 3][n] = br[p].w;
    }
    __syncthreads();

    const int NT = K / BK;
    const int trow = tid / (BN / TN);
    const int tcol = tid % (BN / TN);

    for (int kt = 0; kt < NT; kt++) {
        const int cur = kt & 1;
        if (kt + 1 < NT) {
#pragma unroll
            for (int p = 0; p < AP; p++) ar[p] = *(const float4*)(ap[p] + (kt + 1) * BK);
#pragma unroll
            for (int p = 0; p < BP; p++) br[p] = *(const float4*)(bp[p] + (kt + 1) * BK);
        }
#pragma unroll
        for (int k = 0; k < BK; k++) {
            float a[TM], bf[TN];
#pragma unroll
            for (int i = 0; i < TM; i += 4) {
                float4 v = *(const float4*)&As[cur][k][trow * TM + i];
                a[i] = v.x; a[i + 1] = v.y; a[i + 2] = v.z; a[i + 3] = v.w;
            }
#pragma unroll
            for (int j = 0; j < TN; j += 4) {
                float4 v = *(const float4*)&Bs[cur][k][tcol * TN + j];
                bf[j] = v.x; bf[j + 1] = v.y; bf[j + 2] = v.z; bf[j + 3] = v.w;
            }
#pragma unroll
            for (int i = 0; i < TM; i++)
#pragma unroll
                for (int j = 0; j < TN; j++) acc[i][j] += a[i] * bf[j];
        }
        if (kt + 1 < NT) {
            const int nxt = cur ^ 1;
#pragma unroll
            for (int p = 0; p < AP; p++) {
                int m = lr + p * RPP;
                As[nxt][lk * 4 + 0][m] = ar[p].x; As[nxt][lk * 4 + 1][m] = ar[p].y;
                As[nxt][lk * 4 + 2][m] = ar[p].z; As[nxt][lk * 4 + 3][m] = ar[p].w;
            }
#pragma unroll
            for (int p = 0; p < BP; p++) {
                int n = lr + p * RPP;
                Bs[nxt][lk * 4 + 0][n] = br[p].x; Bs[nxt][lk * 4 + 1][n] = br[p].y;
                Bs[nxt][lk * 4 + 2][n] = br[p].z; Bs[nxt][lk * 4 + 3][n] = br[p].w;
            }
            __syncthreads();
        }
    }

    float bv[TN];
#pragma unroll
    for (int j = 0; j < TN; j++) {
        int n = n0 + tcol * TN + j;
        float v = bias1 ? bias1[n] : 0.0f;
        if (bias2) v += bias2[n];
        bv[j] = v;
    }
#pragma unroll
    for (int i = 0; i < TM; i++) {
        int m = m0 + trow * TM + i;
#pragma unroll
        for (int j = 0; j < TN; j += 4) {
            float4 o;
            o.x = acc[i][j + 0] + bv[j + 0];
            o.y = acc[i][j + 1] + bv[j + 1];
            o.z = acc[i][j + 2] + bv[j + 2];
            o.w = acc[i][j + 3] + bv[j + 3];
            if (act) { o.x = tanhf(o.x); o.y = tanhf(o.y); o.z = tanhf(o.z); o.w = tanhf(o.w); }
            if (Ch) {
                __half* crow = Ch + (size_t)m * N + n0 + tcol * TN;
                *(__half2*)(crow + j) = __halves2half2(__float2half_rn(o.x), __float2half_rn(o.y));
                *(__half2*)(crow + j + 2) = __halves2half2(__float2half_rn(o.z), __float2half_rn(o.w));
            } else {
                float* crow = C + (size_t)m * N + n0 + tcol * TN;
                *(float4*)(crow + j) = o;
            }
        }
    }
}

// ================= RNN recurrence: split-k x2, 512 threads, full fp32 =================
// Thread (j = tid&255, half = tid>>8) computes the partial dot for output j over
// k in [half*128, half*128+128): 88 weights in fp32 REGISTERS + 40 rows in fp32 smem
// (lane-consecutive, conflict-free). h reads are warp-broadcast. Cross-half combine
// through a 1-float smem partial. 16 warps/SM for latency hiding, zero cvts.
#define RNN_WREG 88
#define RNN_WSMR 40                                  // smem rows per half
#define RNN_WSM (2 * RNN_WSMR * 256)                 // floats
#define RNN_SMEM ((RNN_WSM + 256 + 2 * H_) * 4)      // 84992 B

__global__ __launch_bounds__(512) void k_rnn(
    const float* __restrict__ P, const float* __restrict__ W,   // W = W_hh [H][H]
    const int* __restrict__ lengths, const float* __restrict__ h0,
    float* __restrict__ outSeq, float* __restrict__ hFin,
    float* __restrict__ combHalf, int steps) {
    extern __shared__ float sm[];
    float* wsm = sm;                     // [2*RNN_WSMR][256]
    float* partials = sm + RNN_WSM;      // [256]
    float* hs = partials + 256;          // 2 buffers of H_
    const int b = blockIdx.x;
    const int tid = threadIdx.x;
    const int j = tid & 255;
    const int half = tid >> 8;
    const int kbase = half * 128;

    // stage: thread owns row j, k-range [kbase, kbase+128)
    const float* wrow = W + (size_t)j * H_ + kbase;
    float wreg[RNN_WREG];
#pragma unroll
    for (int i = 0; i < RNN_WREG; i += 4) {
        float4 w4 = *(const float4*)(wrow + i);
        wreg[i] = w4.x; wreg[i + 1] = w4.y; wreg[i + 2] = w4.z; wreg[i + 3] = w4.w;
    }
#pragma unroll
    for (int i = 0; i < RNN_WSMR; i++)
        wsm[(half * RNN_WSMR + i) * 256 + j] = wrow[RNN_WREG + i];
    if (half == 0) hs[j] = h0 ? h0[b * H_ + j] : 0.0f;
    __syncthreads();

    const int len = lengths ? lengths[b] : steps;
    const float* Pb = P + (size_t)b * steps * H_;
    float* Ob = outSeq + (size_t)b * steps * H_;
    int cur = 0;

    for (int t = 0; t < steps; t++) {
        const float* hc = hs + cur * H_;
        float pv = 0.0f;
        if (half == 0) pv = Pb[t * H_ + j];   // overlaps with FMA work below
        float a0 = 0.f, a1 = 0.f, a2 = 0.f, a3 = 0.f;
#pragma unroll
        for (int k = 0; k < RNN_WREG; k += 4) {
            float4 h4 = *(const float4*)(hc + kbase + k);
            a0 += h4.x * wreg[k];     a1 += h4.y * wreg[k + 1];
            a2 += h4.z * wreg[k + 2]; a3 += h4.w * wreg[k + 3];
        }
        const float* wsb = wsm + half * RNN_WSMR * 256 + j;
#pragma unroll
        for (int i = 0; i < RNN_WSMR; i += 4) {
            float4 h4 = *(const float4*)(hc + kbase + RNN_WREG + i);
            a0 += h4.x * wsb[(i + 0) * 256];
            a1 += h4.y * wsb[(i + 1) * 256];
            a2 += h4.z * wsb[(i + 2) * 256];
            a3 += h4.w * wsb[(i + 3) * 256];
        }
        float part = (a0 + a1) + (a2 + a3);
        if (half) partials[j] = part;
        __syncthreads();
        if (half == 0) {
            float hv = tanhf(pv + part + partials[j]);
            bool valid = t < len;
            float keep = hc[j];
            hs[(cur ^ 1) * H_ + j] = valid ? hv : keep;
            Ob[t * H_ + j] = valid ? hv : 0.0f;
            if (combHalf)
                combHalf[((size_t)(b * steps + t)) * (2 * H_) + H_ + j] = hv;
        }
        __syncthreads();
        cur ^= 1;
    }
    if (half == 0 && hFin) hFin[b * H_ + j] = hs[cur * H_ + j];
}

// ================= fused attention: scores -> softmax -> context =================
__global__ __launch_bounds__(256) void k_attn(
    const float* __restrict__ Hdec, const float* __restrict__ enc,
    const int* __restrict__ idx_de, float* __restrict__ comb) {
    const int b = blockIdx.x;
    const int t0 = blockIdx.y * 16;
    const int tid = threadIdx.x;
    __shared__ __align__(16) float hs[16][H_];
    __shared__ float sc[16][132];
    __shared__ int msk[S_];

    const float4* Hb4 = (const float4*)(Hdec + ((size_t)b * T_ + t0) * H_);
#pragma unroll
    for (int i = 0; i < 4; i++)
        ((float4*)hs)[tid + i * 256] = Hb4[tid + i * 256];
    if (tid < S_) msk[tid] = idx_de[b * S_ + tid];
    __syncthreads();

    const float* Eb = enc + (size_t)b * S_ * H_;
    {
        const int ti = tid >> 4, sg = tid & 15;
        const float4* h4 = (const float4*)hs[ti];
        for (int r = 0; r < 8; r++) {
            int s = r * 16 + sg;
            const float4* e4 = (const float4*)(Eb + s * H_);
            float a0 = 0.f, a1 = 0.f, a2 = 0.f, a3 = 0.f;
#pragma unroll 8
            for (int k = 0; k < H_ / 4; k++) {
                float4 e = e4[k], h = h4[k];
                a0 += e.x * h.x; a1 += e.y * h.y;
                a2 += e.z * h.z; a3 += e.w * h.w;
            }
            sc[ti][s] = (msk[s] == 0) ? NEGV : ((a0 + a1) + (a2 + a3));
        }
    }
    __syncthreads();
    {
        const int w = tid >> 5, lane = tid & 31;
#pragma unroll
        for (int rr = 0; rr < 2; rr++) {
            int row = w * 2 + rr;
            float v0 = sc[row][lane], v1 = sc[row][lane + 32];
            float v2 = sc[row][lane + 64], v3 = sc[row][lane + 96];
            float m = fmaxf(fmaxf(v0, v1), fmaxf(v2, v3));
#pragma unroll
            for (int o = 16; o > 0; o >>= 1)
                m = fmaxf(m, __shfl_xor_sync(0xffffffffu, m, o));
            float e0 = expf(v0 - m), e1 = expf(v1 - m);
            float e2 = expf(v2 - m), e3 = expf(v3 - m);
            float sum = (e0 + e1) + (e2 + e3);
#pragma unroll
            for (int o = 16; o > 0; o >>= 1)
                sum += __shfl_xor_sync(0xffffffffu, sum, o);
            float inv = 1.0f / sum;
            sc[row][lane] = e0 * inv; sc[row][lane + 32] = e1 * inv;
            sc[row][lane + 64] = e2 * inv; sc[row][lane + 96] = e3 * inv;
        }
    }
    __syncthreads();
    {
        const int ti = tid & 15, jg = tid >> 4;
        float4 c0 = {0, 0, 0, 0}, c1 = c0, c2 = c0, c3 = c0;
        for (int s = 0; s < S_; s++) {
            float p = sc[ti][s];
            const float4* e4 = (const float4*)(Eb + s * H_ + jg * 16);
            float4 e0 = e4[0], e1 = e4[1], e2 = e4[2], e3 = e4[3];
            c0.x += p * e0.x; c0.y += p * e0.y; c0.z += p * e0.z; c0.w += p * e0.w;
            c1.x += p * e1.x; c1.y += p * e1.y; c1.z += p * e1.z; c1.w += p * e1.w;
            c2.x += p * e2.x; c2.y += p * e2.y; c2.z += p * e2.z; c2.w += p * e2.w;
            c3.x += p * e3.x; c3.y += p * e3.y; c3.z += p * e3.z; c3.w += p * e3.w;
        }
        float* dst = comb + ((size_t)(b * T_ + t0 + ti)) * (2 * H_) + jg * 16;
        ((float4*)dst)[0] = c0; ((float4*)dst)[1] = c1;
        ((float4*)dst)[2] = c2; ((float4*)dst)[3] = c3;
    }
}

// ================= launch =================
extern "C" void kernel_launch(void* const* d_in, const int* in_sizes, int n_in,
                              void* d_out, int out_size) {
    const int* indices_de = (const int*)d_in[0];
    const int* lengths_de = (const int*)d_in[1];
    const int* indices_en = (const int*)d_in[2];
    const float* emb_enc = (const float*)d_in[4];
    const float* emb_dec = (const float*)d_in[5];
    const float* W_ih_enc = (const float*)d_in[6];
    const float* W_hh_enc = (const float*)d_in[7];
    const float* b_ih_enc = (const float*)d_in[8];
    const float* b_hh_enc = (const float*)d_in[9];
    const float* W_ih_dec = (const float*)d_in[10];
    const float* W_hh_dec = (const float*)d_in[11];
    const float* b_ih_dec = (const float*)d_in[12];
    const float* b_hh_dec = (const float*)d_in[13];
    const float* W_attn = (const float*)d_in[14];
    const float* b_attn = (const float*)d_in[15];
    const float* W_out = (const float*)d_in[16];
    const float* b_out = (const float*)d_in[17];
    float* out = (float*)d_out;

    float *pPe, *pPd, *pEnc, *pHf, *pHd, *pComb;
    __half *pWh, *pAh;
    cudaGetSymbolAddress((void**)&pPe, g_P_enc);
    cudaGetSymbolAddress((void**)&pPd, g_P_dec);
    cudaGetSymbolAddress((void**)&pEnc, g_enc_out);
    cudaGetSymbolAddress((void**)&pHf, g_h_final);
    cudaGetSymbolAddress((void**)&pHd, g_Hdec);
    cudaGetSymbolAddress((void**)&pComb, g_comb);
    cudaGetSymbolAddress((void**)&pWh, g_Wh);
    cudaGetSymbolAddress((void**)&pAh, g_Ah);

    cudaFuncSetAttribute(k_logits_mma, cudaFuncAttributeMaxDynamicSharedMemorySize,
                         SMEM_LOGITS);
    cudaFuncSetAttribute(k_rnn, cudaFuncAttributeMaxDynamicSharedMemorySize,
                         RNN_SMEM);

    // 1. convert W_out to fp16
    k_cvt4h<<<(V_ * H_ / 4) / 256, 256>>>((const float4*)W_out, pWh);

    // 2. batched input projections (embedding gather fused into GEMM)
    k_gemm<64, 64, 16, 4, 4><<<dim3(H_ / 64, (B_ * S_) / 64), 256>>>(
        B_ * S_, H_, E_, emb_enc, indices_de, W_ih_enc, pPe, b_ih_enc, b_hh_enc, 0, nullptr);
    k_gemm<64, 64, 16, 4, 4><<<dim3(H_ / 64, (B_ * T_) / 64), 256>>>(
        B_ * T_, H_, E_, emb_dec, indices_en, W_ih_dec, pPd, b_ih_dec, b_hh_dec, 0, nullptr);

    // 3. sequential recurrences (split-k x2, 16 warps, weights reg+smem resident)
    k_rnn<<<B_, 512, RNN_SMEM>>>(pPe, W_hh_enc, lengths_de, nullptr, pEnc, pHf, nullptr, S_);
    k_rnn<<<B_, 512, RNN_SMEM>>>(pPd, W_hh_dec, nullptr, pHf, pHd, nullptr, pComb, T_);

    // 4. attention -> context into comb[:, 0:H]
    k_attn<<<dim3(B_, T_ / 16), 256>>>(pHd, pEnc, indices_de, pComb);

    // 5. attn_out = tanh([context|h] @ W_attn^T + b_attn), written directly as fp16
    k_gemm<64, 64, 16, 4, 4><<<dim3(H_ / 64, (B_ * T_) / 64), 256>>>(
        B_ * T_, H_, 2 * H_, pComb, nullptr, W_attn, nullptr, b_attn, nullptr, 1, pAh);

    // 6. mma.sync fp16 logits GEMM
    k_logits_mma<<<dim3((B_ * T_) / 128, V_ / 128), 256, SMEM_LOGITS>>>(
        pAh, pWh, b_out, out);
}

// round 11
// speedup vs baseline: 1.2426x; 1.0552x over previous
#include <cuda_runtime.h>
#include <cuda_fp16.h>
#include <cstdint>
#include <cstddef>

#define B_ 32
#define S_ 128
#define T_ 128
#define V_ 32000
#define E_ 256
#define H_ 256
#define NEGV -1.0e9f

// ================= scratch (static device memory; no allocation) =================
__device__ float g_P_enc[B_ * S_ * H_];
__device__ float g_P_dec[B_ * T_ * H_];
__device__ float g_enc_out[B_ * S_ * H_];
__device__ float g_h_final[B_ * H_];
__device__ float g_Hdec[B_ * T_ * H_];
__device__ float g_comb[B_ * T_ * 2 * H_];
__device__ __half g_Wh[V_ * H_];           // W_out in fp16
__device__ __half g_Ah[B_ * T_ * H_];      // attn_out in fp16

// ================= PTX helpers (sm_80-compatible only; no 'a' features) =================
__device__ __forceinline__ uint32_t smem_u32(const void* p) {
    uint32_t a;
    asm("{ .reg .u64 t; cvta.to.shared.u64 t, %1; cvt.u32.u64 %0, t; }" : "=r"(a) : "l"(p));
    return a;
}
#define CP_ASYNC16(saddr, gaddr) \
    asm volatile("cp.async.cg.shared.global [%0], [%1], 16;" :: "r"(saddr), "l"(gaddr))
#define CP_COMMIT() asm volatile("cp.async.commit_group;")
#define CP_WAIT0()  asm volatile("cp.async.wait_group 0;")
#define LDSM_X4(r, addr) \
    asm volatile("ldmatrix.sync.aligned.m8n8.x4.shared.b16 {%0,%1,%2,%3}, [%4];" \
        : "=r"((r)[0]), "=r"((r)[1]), "=r"((r)[2]), "=r"((r)[3]) : "r"(addr))
#define MMA16816F16(d, a, b) \
    asm volatile("mma.sync.aligned.m16n8k16.row.col.f32.f16.f16.f32 " \
        "{%0,%1,%2,%3}, {%4,%5,%6,%7}, {%8,%9}, {%0,%1,%2,%3};" \
        : "+f"((d)[0]), "+f"((d)[1]), "+f"((d)[2]), "+f"((d)[3]) \
        : "r"((a)[0]), "r"((a)[1]), "r"((a)[2]), "r"((a)[3]), "r"((b)[0]), "r"((b)[1]))

// ================= fp32 -> fp16 convert (vector of 4) =================
__global__ void k_cvt4h(const float4* __restrict__ x, __half* __restrict__ o) {
    int i = blockIdx.x * blockDim.x + threadIdx.x;
    float4 v = x[i];
    __half2* O = (__half2*)(o + (size_t)i * 4);
    O[0] = __halves2half2(__float2half_rn(v.x), __float2half_rn(v.y));
    O[1] = __halves2half2(__float2half_rn(v.z), __float2half_rn(v.w));
}

// ================= mma.sync fp16 logits GEMM =================
#define LG_STRIDE 144
#define LG_MAT (128 * LG_STRIDE)
#define LG_A 0
#define LG_W (LG_MAT)
#define LG_BUF (2 * LG_MAT)               // 36864 B per buffer
#define SMEM_LOGITS (2 * LG_BUF)          // 73728 B

__device__ __forceinline__ void lg_load(
    uint32_t sb, const __half* __restrict__ Ah, const __half* __restrict__ Wh,
    int m0, int n0, int kc, int tid) {
#pragma unroll
    for (int i = 0; i < 4; i++) {
        int idx = tid + i * 256;
        int r = idx >> 3, c = idx & 7;
        uint32_t soff = r * LG_STRIDE + c * 16;
        size_t ga = (size_t)(m0 + r) * H_ + kc * 64 + c * 8;
        size_t gw = (size_t)(n0 + r) * H_ + kc * 64 + c * 8;
        CP_ASYNC16(sb + LG_A + soff, Ah + ga);
        CP_ASYNC16(sb + LG_W + soff, Wh + gw);
    }
}

__global__ __launch_bounds__(256, 2) void k_logits_mma(
    const __half* __restrict__ Ah, const __half* __restrict__ Wh,
    const float* __restrict__ bias, float* __restrict__ out) {
    extern __shared__ char smem[];
    const uint32_t sbase = smem_u32(smem);
    const int tid = threadIdx.x, wid = tid >> 5, lane = tid & 31;
    const int warp_m = wid & 3, warp_n = wid >> 2;
    const int m0 = blockIdx.x * 128;
    const int n0 = blockIdx.y * 128;

    float acc[2][8][4];
#pragma unroll
    for (int mt = 0; mt < 2; mt++)
#pragma unroll
        for (int nt = 0; nt < 8; nt++)
#pragma unroll
            for (int q = 0; q < 4; q++) acc[mt][nt][q] = 0.0f;

    lg_load(sbase, Ah, Wh, m0, n0, 0, tid);
    CP_COMMIT();
    CP_WAIT0();
    __syncthreads();

    const int g = lane >> 3, r8 = lane & 7;
    const uint32_t a_off = (uint32_t)(warp_m * 32 + (g & 1) * 8 + r8) * LG_STRIDE +
                           (uint32_t)((g >> 1) * 8) * 2;
    const uint32_t b_off = (uint32_t)(warp_n * 64 + (g >> 1) * 8 + r8) * LG_STRIDE +
                           (uint32_t)((g & 1) * 8) * 2;

    for (int kc = 0; kc < 4; kc++) {
        const uint32_t buf = sbase + (kc & 1) * LG_BUF;
        if (kc < 3) {
            lg_load(sbase + ((kc + 1) & 1) * LG_BUF, Ah, Wh, m0, n0, kc + 1, tid);
            CP_COMMIT();
        }
#pragma unroll
        for (int ks = 0; ks < 4; ks++) {
            const uint32_t koff = (uint32_t)(ks * 16) * 2;
            uint32_t af[2][4], bf[8][2];
#pragma unroll
            for (int p = 0; p < 4; p++) {
                uint32_t t[4];
                LDSM_X4(t, buf + LG_W + b_off + p * (16 * LG_STRIDE) + koff);
                bf[2 * p][0] = t[0]; bf[2 * p][1] = t[1];
                bf[2 * p + 1][0] = t[2]; bf[2 * p + 1][1] = t[3];
            }
#pragma unroll
            for (int mt = 0; mt < 2; mt++)
                LDSM_X4(af[mt], buf + LG_A + a_off + mt * (16 * LG_STRIDE) + koff);
#pragma unroll
            for (int mt = 0; mt < 2; mt++)
#pragma unroll
                for (int nt = 0; nt < 8; nt++) MMA16816F16(acc[mt][nt], af[mt], bf[nt]);
        }
        if (kc < 3) {
            CP_WAIT0();
            __syncthreads();
        }
    }

    const int er = lane >> 2, ec = (lane & 3) * 2;
#pragma unroll
    for (int mt = 0; mt < 2; mt++) {
        const int row0 = m0 + warp_m * 32 + mt * 16 + er;
#pragma unroll
        for (int nt = 0; nt < 8; nt++) {
            const int col0 = n0 + warp_n * 64 + nt * 8 + ec;
            float2 bb = *(const float2*)(bias + col0);
            float2 o0, o1;
            o0.x = acc[mt][nt][0] + bb.x; o0.y = acc[mt][nt][1] + bb.y;
            o1.x = acc[mt][nt][2] + bb.x; o1.y = acc[mt][nt][3] + bb.y;
            *(float2*)(out + (size_t)row0 * V_ + col0) = o0;
            *(float2*)(out + (size_t)(row0 + 8) * V_ + col0) = o1;
        }
    }
}

// ================= generic fp32 SIMT GEMM (small ops only) =================
// grid.z selects parameter set (z=1 uses the *_b set) so independent same-shape
// GEMMs share one launch. If Ch != nullptr, writes fp16 output instead of fp32 C.
template <int BM, int BN, int BK, int TM, int TN>
__global__ __launch_bounds__(256) void k_gemm(
    int M, int N, int K,
    const float* A_, const int* gidx_, const float* Bm_, float* C_,
    const float* bias1_, const float* bias2_, int act, __half* Ch_,
    const float* A_b, const int* gidx_b, const float* Bm_b, float* C_b,
    const float* bias1_b, const float* bias2_b) {
    const float* A = A_; const int* gidx = gidx_; const float* Bm = Bm_;
    float* C = C_; const float* bias1 = bias1_; const float* bias2 = bias2_;
    __half* Ch = Ch_;
    if (blockIdx.z == 1) {
        A = A_b; gidx = gidx_b; Bm = Bm_b; C = C_b; bias1 = bias1_b; bias2 = bias2_b;
        Ch = nullptr;
    }
    constexpr int KV = BK / 4;
    constexpr int RPP = 256 / KV;
    constexpr int AP = BM / RPP;
    constexpr int BP = BN / RPP;

    __shared__ __align__(16) float As[2][BK][BM];
    __shared__ __align__(16) float Bs[2][BK][BN];

    const int tid = threadIdx.x;
    const int m0 = blockIdx.y * BM;
    const int n0 = blockIdx.x * BN;
    const int lr = tid / KV;
    const int lk = tid % KV;

    const float* ap[AP];
    const float* bp[BP];
#pragma unroll
    for (int p = 0; p < AP; p++) {
        int gm = m0 + lr + p * RPP;
        int grow = gidx ? gidx[gm] : gm;
        ap[p] = A + (size_t)grow * K + lk * 4;
    }
#pragma unroll
    for (int p = 0; p < BP; p++)
        bp[p] = Bm + (size_t)(n0 + lr + p * RPP) * K + lk * 4;

    float acc[TM][TN];
#pragma unroll
    for (int i = 0; i < TM; i++)
#pragma unroll
        for (int j = 0; j < TN; j++) acc[i][j] = 0.0f;

    float4 ar[AP], br[BP];
#pragma unroll
    for (int p = 0; p < AP; p++) ar[p] = *(const float4*)(ap[p]);
#pragma unroll
    for (int p = 0; p < BP; p++) br[p] = *(const float4*)(bp[p]);
#pragma unroll
    for (int p = 0; p < AP; p++) {
        int m = lr + p * RPP;
        As[0][lk * 4 + 0][m] = ar[p].x; As[0][lk * 4 + 1][m] = ar[p].y;
        As[0][lk * 4 + 2][m] = ar[p].z; As[0][lk * 4 + 3][m] = ar[p].w;
    }
#pragma unroll
    for (int p = 0; p < BP; p++) {
        int n = lr + p * RPP;
        Bs[0][lk * 4 + 0][n] = br[p].x; Bs[0][lk * 4 + 1][n] = br[p].y;
        Bs[0][lk * 4 + 2][n] = br[p].z; Bs[0][lk * 4 + 3][n] = br[p].w;
    }
    __syncthreads();

    const int NT = K / BK;
    const int trow = tid / (BN / TN);
    const int tcol = tid % (BN / TN);

    for (int kt = 0; kt < NT; kt++) {
        const int cur = kt & 1;
        if (kt + 1 < NT) {
#pragma unroll
            for (int p = 0; p < AP; p++) ar[p] = *(const float4*)(ap[p] + (kt + 1) * BK);
#pragma unroll
            for (int p = 0; p < BP; p++) br[p] = *(const float4*)(bp[p] + (kt + 1) * BK);
        }
#pragma unroll
        for (int k = 0; k < BK; k++) {
            float a[TM], bf[TN];
#pragma unroll
            for (int i = 0; i < TM; i += 4) {
                float4 v = *(const float4*)&As[cur][k][trow * TM + i];
                a[i] = v.x; a[i + 1] = v.y; a[i + 2] = v.z; a[i + 3] = v.w;
            }
#pragma unroll
            for (int j = 0; j < TN; j += 4) {
                float4 v = *(const float4*)&Bs[cur][k][tcol * TN + j];
                bf[j] = v.x; bf[j + 1] = v.y; bf[j + 2] = v.z; bf[j + 3] = v.w;
            }
#pragma unroll
            for (int i = 0; i < TM; i++)
#pragma unroll
                for (int j = 0; j < TN; j++) acc[i][j] += a[i] * bf[j];
        }
        if (kt + 1 < NT) {
            const int nxt = cur ^ 1;
#pragma unroll
            for (int p = 0; p < AP; p++) {
                int m = lr + p * RPP;
                As[nxt][lk * 4 + 0][m] = ar[p].x; As[nxt][lk * 4 + 1][m] = ar[p].y;
                As[nxt][lk * 4 + 2][m] = ar[p].z; As[nxt][lk * 4 + 3][m] = ar[p].w;
            }
#pragma unroll
            for (int p = 0; p < BP; p++) {
                int n = lr + p * RPP;
                Bs[nxt][lk * 4 + 0][n] = br[p].x; Bs[nxt][lk * 4 + 1][n] = br[p].y;
                Bs[nxt][lk * 4 + 2][n] = br[p].z; Bs[nxt][lk * 4 + 3][n] = br[p].w;
            }
            __syncthreads();
        }
    }

    float bv[TN];
#pragma unroll
    for (int j = 0; j < TN; j++) {
        int n = n0 + tcol * TN + j;
        float v = bias1 ? bias1[n] : 0.0f;
        if (bias2) v += bias2[n];
        bv[j] = v;
    }
#pragma unroll
    for (int i = 0; i < TM; i++) {
        int m = m0 + trow * TM + i;
#pragma unroll
        for (int j = 0; j < TN; j += 4) {
            float4 o;
            o.x = acc[i][j + 0] + bv[j + 0];
            o.y = acc[i][j + 1] + bv[j + 1];
            o.z = acc[i][j + 2] + bv[j + 2];
            o.w = acc[i][j + 3] + bv[j + 3];
            if (act) { o.x = tanhf(o.x); o.y = tanhf(o.y); o.z = tanhf(o.z); o.w = tanhf(o.w); }
            if (Ch) {
                __half* crow = Ch + (size_t)m * N + n0 + tcol * TN;
                *(__half2*)(crow + j) = __halves2half2(__float2half_rn(o.x), __float2half_rn(o.y));
                *(__half2*)(crow + j + 2) = __halves2half2(__float2half_rn(o.z), __float2half_rn(o.w));
            } else {
                float* crow = C + (size_t)m * N + n0 + tcol * TN;
                *(float4*)(crow + j) = o;
            }
        }
    }
}

// ================= RNN recurrence: split-k x2, 512 threads =================
// Thread (j = tid&255, half = tid>>8) computes the partial dot for output j over
// k in [half*128, half*128+128): 88 weights in fp32 REGISTERS (exact) + 40 values
// packed as 20 fp16 half2 in smem (lane-consecutive 4B reads -> half the crossbar
// phases of fp32). fp32 accumulation. Cross-half combine via 1-float smem partial.
#define RNN_WREG 88
#define RNN_WP 20                                    // half2 pairs per half per j
#define RNN_WSM (2 * RNN_WP * 256)                   // half2 count
#define RNN_SMEM ((RNN_WSM + 256 + 2 * H_) * 4)      // 43, + partials + h = 44032 B

__global__ __launch_bounds__(512) void k_rnn(
    const float* __restrict__ P, const float* __restrict__ W,   // W = W_hh [H][H]
    const int* __restrict__ lengths, const float* __restrict__ h0,
    float* __restrict__ outSeq, float* __restrict__ hFin,
    float* __restrict__ combHalf, int steps) {
    extern __shared__ float sm[];
    __half2* wsm = (__half2*)sm;         // [2*RNN_WP][256]
    float* partials = sm + RNN_WSM;      // [256]
    float* hs = partials + 256;          // 2 buffers of H_
    const int b = blockIdx.x;
    const int tid = threadIdx.x;
    const int j = tid & 255;
    const int half = tid >> 8;
    const int kbase = half * 128;

    // stage: thread owns row j, k-range [kbase, kbase+128)
    const float* wrow = W + (size_t)j * H_ + kbase;
    float wreg[RNN_WREG];
#pragma unroll
    for (int i = 0; i < RNN_WREG; i += 4) {
        float4 w4 = *(const float4*)(wrow + i);
        wreg[i] = w4.x; wreg[i + 1] = w4.y; wreg[i + 2] = w4.z; wreg[i + 3] = w4.w;
    }
#pragma unroll
    for (int i = 0; i < RNN_WP; i++) {
        float2 w2 = *(const float2*)(wrow + RNN_WREG + 2 * i);
        wsm[(half * RNN_WP + i) * 256 + j] = __floats2half2_rn(w2.x, w2.y);
    }
    if (half == 0) hs[j] = h0 ? h0[b * H_ + j] : 0.0f;
    __syncthreads();

    const int len = lengths ? lengths[b] : steps;
    const float* Pb = P + (size_t)b * steps * H_;
    float* Ob = outSeq + (size_t)b * steps * H_;
    int cur = 0;

    for (int t = 0; t < steps; t++) {
        const float* hc = hs + cur * H_;
        float pv = 0.0f;
        if (half == 0) pv = Pb[t * H_ + j];   // overlaps with FMA work below
        float a0 = 0.f, a1 = 0.f, a2 = 0.f, a3 = 0.f;
#pragma unroll
        for (int k = 0; k < RNN_WREG; k += 4) {
            float4 h4 = *(const float4*)(hc + kbase + k);
            a0 += h4.x * wreg[k];     a1 += h4.y * wreg[k + 1];
            a2 += h4.z * wreg[k + 2]; a3 += h4.w * wreg[k + 3];
        }
        const __half2* wsb = wsm + half * RNN_WP * 256 + j;
#pragma unroll
        for (int i = 0; i < RNN_WP; i += 2) {
            float4 h4 = *(const float4*)(hc + kbase + RNN_WREG + 2 * i);
            float2 fa = __half22float2(wsb[(i + 0) * 256]);
            float2 fb = __half22float2(wsb[(i + 1) * 256]);
            a0 += h4.x * fa.x; a1 += h4.y * fa.y;
            a2 += h4.z * fb.x; a3 += h4.w * fb.y;
        }
        float part = (a0 + a1) + (a2 + a3);
        if (half) partials[j] = part;
        __syncthreads();
        if (half == 0) {
            float hv = tanhf(pv + part + partials[j]);
            bool valid = t < len;
            float keep = hc[j];
            hs[(cur ^ 1) * H_ + j] = valid ? hv : keep;
            Ob[t * H_ + j] = valid ? hv : 0.0f;
            if (combHalf)
                combHalf[((size_t)(b * steps + t)) * (2 * H_) + H_ + j] = hv;
        }
        __syncthreads();
        cur ^= 1;
    }
    if (half == 0 && hFin) hFin[b * H_ + j] = hs[cur * H_ + j];
}

// ================= fused attention: scores -> softmax -> context =================
__global__ __launch_bounds__(256) void k_attn(
    const float* __restrict__ Hdec, const float* __restrict__ enc,
    const int* __restrict__ idx_de, float* __restrict__ comb) {
    const int b = blockIdx.x;
    const int t0 = blockIdx.y * 16;
    const int tid = threadIdx.x;
    __shared__ __align__(16) float hs[16][H_];
    __shared__ float sc[16][132];
    __shared__ int msk[S_];

    const float4* Hb4 = (const float4*)(Hdec + ((size_t)b * T_ + t0) * H_);
#pragma unroll
    for (int i = 0; i < 4; i++)
        ((float4*)hs)[tid + i * 256] = Hb4[tid + i * 256];
    if (tid < S_) msk[tid] = idx_de[b * S_ + tid];
    __syncthreads();

    const float* Eb = enc + (size_t)b * S_ * H_;
    {
        const int ti = tid >> 4, sg = tid & 15;
        const float4* h4 = (const float4*)hs[ti];
        for (int r = 0; r < 8; r++) {
            int s = r * 16 + sg;
            const float4* e4 = (const float4*)(Eb + s * H_);
            float a0 = 0.f, a1 = 0.f, a2 = 0.f, a3 = 0.f;
#pragma unroll 8
            for (int k = 0; k < H_ / 4; k++) {
                float4 e = e4[k], h = h4[k];
                a0 += e.x * h.x; a1 += e.y * h.y;
                a2 += e.z * h.z; a3 += e.w * h.w;
            }
            sc[ti][s] = (msk[s] == 0) ? NEGV : ((a0 + a1) + (a2 + a3));
        }
    }
    __syncthreads();
    {
        const int w = tid >> 5, lane = tid & 31;
#pragma unroll
        for (int rr = 0; rr < 2; rr++) {
            int row = w * 2 + rr;
            float v0 = sc[row][lane], v1 = sc[row][lane + 32];
            float v2 = sc[row][lane + 64], v3 = sc[row][lane + 96];
            float m = fmaxf(fmaxf(v0, v1), fmaxf(v2, v3));
#pragma unroll
            for (int o = 16; o > 0; o >>= 1)
                m = fmaxf(m, __shfl_xor_sync(0xffffffffu, m, o));
            float e0 = expf(v0 - m), e1 = expf(v1 - m);
            float e2 = expf(v2 - m), e3 = expf(v3 - m);
            float sum = (e0 + e1) + (e2 + e3);
#pragma unroll
            for (int o = 16; o > 0; o >>= 1)
                sum += __shfl_xor_sync(0xffffffffu, sum, o);
            float inv = 1.0f / sum;
            sc[row][lane] = e0 * inv; sc[row][lane + 32] = e1 * inv;
            sc[row][lane + 64] = e2 * inv; sc[row][lane + 96] = e3 * inv;
        }
    }
    __syncthreads();
    {
        const int ti = tid & 15, jg = tid >> 4;
        float4 c0 = {0, 0, 0, 0}, c1 = c0, c2 = c0, c3 = c0;
        for (int s = 0; s < S_; s++) {
            float p = sc[ti][s];
            const float4* e4 = (const float4*)(Eb + s * H_ + jg * 16);
            float4 e0 = e4[0], e1 = e4[1], e2 = e4[2], e3 = e4[3];
            c0.x += p * e0.x; c0.y += p * e0.y; c0.z += p * e0.z; c0.w += p * e0.w;
            c1.x += p * e1.x; c1.y += p * e1.y; c1.z += p * e1.z; c1.w += p * e1.w;
            c2.x += p * e2.x; c2.y += p * e2.y; c2.z += p * e2.z; c2.w += p * e2.w;
            c3.x += p * e3.x; c3.y += p * e3.y; c3.z += p * e3.z; c3.w += p * e3.w;
        }
        float* dst = comb + ((size_t)(b * T_ + t0 + ti)) * (2 * H_) + jg * 16;
        ((float4*)dst)[0] = c0; ((float4*)dst)[1] = c1;
        ((float4*)dst)[2] = c2; ((float4*)dst)[3] = c3;
    }
}

// ================= launch =================
extern "C" void kernel_launch(void* const* d_in, const int* in_sizes, int n_in,
                              void* d_out, int out_size) {
    const int* indices_de = (const int*)d_in[0];
    const int* lengths_de = (const int*)d_in[1];
    const int* indices_en = (const int*)d_in[2];
    const float* emb_enc = (const float*)d_in[4];
    const float* emb_dec = (const float*)d_in[5];
    const float* W_ih_enc = (const float*)d_in[6];
    const float* W_hh_enc = (const float*)d_in[7];
    const float* b_ih_enc = (const float*)d_in[8];
    const float* b_hh_enc = (const float*)d_in[9];
    const float* W_ih_dec = (const float*)d_in[10];
    const float* W_hh_dec = (const float*)d_in[11];
    const float* b_ih_dec = (const float*)d_in[12];
    const float* b_hh_dec = (const float*)d_in[13];
    const float* W_attn = (const float*)d_in[14];
    const float* b_attn = (const float*)d_in[15];
    const float* W_out = (const float*)d_in[16];
    const float* b_out = (const float*)d_in[17];
    float* out = (float*)d_out;

    float *pPe, *pPd, *pEnc, *pHf, *pHd, *pComb;
    __half *pWh, *pAh;
    cudaGetSymbolAddress((void**)&pPe, g_P_enc);
    cudaGetSymbolAddress((void**)&pPd, g_P_dec);
    cudaGetSymbolAddress((void**)&pEnc, g_enc_out);
    cudaGetSymbolAddress((void**)&pHf, g_h_final);
    cudaGetSymbolAddress((void**)&pHd, g_Hdec);
    cudaGetSymbolAddress((void**)&pComb, g_comb);
    cudaGetSymbolAddress((void**)&pWh, g_Wh);
    cudaGetSymbolAddress((void**)&pAh, g_Ah);

    cudaFuncSetAttribute(k_logits_mma, cudaFuncAttributeMaxDynamicSharedMemorySize,
                         SMEM_LOGITS);
    cudaFuncSetAttribute(k_rnn, cudaFuncAttributeMaxDynamicSharedMemorySize,
                         RNN_SMEM);

    // 1. convert W_out to fp16
    k_cvt4h<<<(V_ * H_ / 4) / 256, 256>>>((const float4*)W_out, pWh);

    // 2. both input projections in ONE launch (grid.z selects enc/dec param set)
    k_gemm<64, 64, 16, 4, 4><<<dim3(H_ / 64, (B_ * S_) / 64, 2), 256>>>(
        B_ * S_, H_, E_,
        emb_enc, indices_de, W_ih_enc, pPe, b_ih_enc, b_hh_enc, 0, nullptr,
        emb_dec, indices_en, W_ih_dec, pPd, b_ih_dec, b_hh_dec);

    // 3. sequential recurrences (split-k x2, weights reg(fp32)+smem(fp16) resident)
    k_rnn<<<B_, 512, RNN_SMEM>>>(pPe, W_hh_enc, lengths_de, nullptr, pEnc, pHf, nullptr, S_);
    k_rnn<<<B_, 512, RNN_SMEM>>>(pPd, W_hh_dec, nullptr, pHf, pHd, nullptr, pComb, T_);

    // 4. attention -> context into comb[:, 0:H]
    k_attn<<<dim3(B_, T_ / 16), 256>>>(pHd, pEnc, indices_de, pComb);

    // 5. attn_out = tanh([context|h] @ W_attn^T + b_attn), written directly as fp16
    k_gemm<64, 64, 16, 4, 4><<<dim3(H_ / 64, (B_ * T_) / 64, 1), 256>>>(
        B_ * T_, H_, 2 * H_,
        pComb, nullptr, W_attn, nullptr, b_attn, nullptr, 1, pAh,
        nullptr, nullptr, nullptr, nullptr, nullptr, nullptr);

    // 6. mma.sync fp16 logits GEMM
    k_logits_mma<<<dim3((B_ * T_) / 128, V_ / 128), 256, SMEM_LOGITS>>>(
        pAh, pWh, b_out, out);
}